// round 9
// baseline (speedup 1.0000x reference)
#include <cuda_runtime.h>

#define N_RAYS   8192
#define P        256
#define HID      64
#define OUTW     261   // 3 rgb + depth + missed + 256 probs
#define FULL     0xffffffffu

__device__ __forceinline__ float4 f4add(float4 a, float4 b) {
    return make_float4(a.x + b.x, a.y + b.y, a.z + b.z, a.w + b.w);
}
__device__ __forceinline__ float4 shflup4(float4 v, int off) {
    return make_float4(__shfl_up_sync(FULL, v.x, off), __shfl_up_sync(FULL, v.y, off),
                       __shfl_up_sync(FULL, v.z, off), __shfl_up_sync(FULL, v.w, off));
}
__device__ __forceinline__ float fast_sigmoid(float x) {
    float t;
    asm("tanh.approx.f32 %0, %1;" : "=f"(t) : "f"(0.5f * x));
    return fmaf(t, 0.5f, 0.5f);
}

__global__ __launch_bounds__(256, 6) void vr_kernel(
    const float* __restrict__ ray_start,   // [N,3]
    const float* __restrict__ ray_dir,     // [N,3]
    const float* __restrict__ depth,       // [N,P]
    const float* __restrict__ dists,       // [N,P]
    const int*   __restrict__ sidx,        // [N,P]
    const float* __restrict__ W1,          // [3,HID]
    const float* __restrict__ b1,          // [HID]
    const float* __restrict__ w_sigma,     // [HID]
    const float* __restrict__ W_rgb,       // [HID,3]
    const float* __restrict__ W_dir,       // [3,3]
    const float* __restrict__ b_rgb,       // [3]
    float*       __restrict__ out)         // [N,OUTW]
{
    __shared__ float  s_ts[8][64];
    __shared__ float4 s_TS[8][65];    // totN_S + signed prefix (sig,r0,r1,r2)
    __shared__ float4 s_TD[8][65];
    __shared__ float  s_q [8][288];   // unscaled q staging, stride-9 per owner lane
    __shared__ float  s_ex[8][32];    // per-lane exclusive transmittance

    const int tid  = threadIdx.x;
    const int w    = tid >> 5;
    const int lane = tid & 31;
    const int ray  = blockIdx.x * 8 + w;

    // --- per-ray scalars ---
    const float rs0 = ray_start[ray * 3 + 0];
    const float rs1 = ray_start[ray * 3 + 1];
    const float rs2 = ray_start[ray * 3 + 2];
    const float rd0 = ray_dir[ray * 3 + 0];
    const float rd1 = ray_dir[ray * 3 + 1];
    const float rd2 = ray_dir[ray * 3 + 2];

    // --- per-unit setup: lane owns units uA=lane, uB=lane+32 ---
    float kA, kB;
    float4 sgSA, sgDA, sgSB, sgDB;
    float4 negS = make_float4(0.f, 0.f, 0.f, 0.f);
    float4 negD = make_float4(0.f, 0.f, 0.f, 0.f);

#pragma unroll
    for (int half = 0; half < 2; ++half) {
        const int u = lane + half * 32;
        const float w1x = W1[u], w1y = W1[HID + u], w1z = W1[2 * HID + u];
        const float S = b1[u] + rs0 * w1x + rs1 * w1y + rs2 * w1z;
        const float D = rd0 * w1x + rd1 * w1y + rd2 * w1z;
        const float wsg = w_sigma[u];
        const float wr0 = W_rgb[u * 3 + 0];
        const float wr1 = W_rgb[u * 3 + 1];
        const float wr2 = W_rgb[u * 3 + 2];
        float t;
        int isPos;
        if (D > 0.f)      { t = __fdividef(-S, D); isPos = 1; }
        else if (D < 0.f) { t = __fdividef(-S, D); isPos = 0; }
        else              { t = (S > 0.f) ? -1e30f : 1e30f; isPos = 1; }
        const float sgn = isPos ? 1.f : -1.f;
        float4 pS = make_float4(wsg * S, wr0 * S, wr1 * S, wr2 * S);
        float4 pD = make_float4(wsg * D, wr0 * D, wr1 * D, wr2 * D);
        if (!isPos) {
            negS = f4add(negS, pS);
            negD = f4add(negD, pD);
        }
        float4 gS = make_float4(sgn * pS.x, sgn * pS.y, sgn * pS.z, sgn * pS.w);
        float4 gD = make_float4(sgn * pD.x, sgn * pD.y, sgn * pD.z, sgn * pD.w);
        if (half == 0) { kA = t; sgSA = gS; sgDA = gD; }
        else           { kB = t; sgSB = gS; sgDB = gD; }
    }

    // --- warp reduction: neg-group totals (8 channels) ---
#pragma unroll
    for (int off = 16; off; off >>= 1) {
        negS.x += __shfl_xor_sync(FULL, negS.x, off);
        negS.y += __shfl_xor_sync(FULL, negS.y, off);
        negS.z += __shfl_xor_sync(FULL, negS.z, off);
        negS.w += __shfl_xor_sync(FULL, negS.w, off);
        negD.x += __shfl_xor_sync(FULL, negD.x, off);
        negD.y += __shfl_xor_sync(FULL, negD.y, off);
        negD.z += __shfl_xor_sync(FULL, negD.z, off);
        negD.w += __shfl_xor_sync(FULL, negD.w, off);
    }

    // --- counting rank (ties by id) ---
    int rA = 0, rB = 0;
#pragma unroll
    for (int src = 0; src < 32; ++src) {
        const float oA = __shfl_sync(FULL, kA, src);
        const float oB = __shfl_sync(FULL, kB, src);
        rA += (oA < kA) | ((oA == kA) & (src < lane));
        rA += (oB < kA);
        rB += (oA < kB) | (oA == kB);
        rB += (oB < kB) | ((oB == kB) & (src < lane));
    }

    // --- scatter signed payloads into sorted slots ---
    s_ts[w][rA] = kA;
    s_TS[w][rA] = sgSA;
    s_TD[w][rA] = sgDA;
    s_ts[w][rB] = kB;
    s_TS[w][rB] = sgSB;
    s_TD[w][rB] = sgDB;
    __syncwarp();

    // --- 8-channel exclusive scan over 64 slots, bake totN into base ---
    const int p0 = 2 * lane, p1 = p0 + 1;
    const float4 aS0 = s_TS[w][p0], aS1 = s_TS[w][p1];
    const float4 aD0 = s_TD[w][p0], aD1 = s_TD[w][p1];

    float4 iS = f4add(aS0, aS1);
    float4 iD = f4add(aD0, aD1);
#pragma unroll
    for (int off = 1; off < 32; off <<= 1) {
        float4 tS = shflup4(iS, off);
        float4 tD = shflup4(iD, off);
        if (lane >= off) {
            iS = f4add(iS, tS);
            iD = f4add(iD, tD);
        }
    }
    float4 eS = shflup4(iS, 1);
    float4 eD = shflup4(iD, 1);
    if (lane == 0) {
        eS = make_float4(0.f, 0.f, 0.f, 0.f);
        eD = make_float4(0.f, 0.f, 0.f, 0.f);
    }
    __syncwarp();
    const float4 b0S = f4add(negS, eS);
    const float4 b0D = f4add(negD, eD);
    s_TS[w][p0] = b0S;  s_TS[w][p1] = f4add(b0S, aS0);
    s_TD[w][p0] = b0D;  s_TD[w][p1] = f4add(b0D, aD0);
    if (lane == 31) {
        s_TS[w][64] = f4add(negS, iS);
        s_TD[w][64] = f4add(negD, iD);
    }
    __syncwarp();

    // --- load this lane's 8 contiguous samples ---
    const int base = ray * P + lane * 8;
    const float4 dA4 = *(const float4*)(depth + base);
    const float4 dB4 = *(const float4*)(depth + base + 4);
    const float dep[8] = {dA4.x, dA4.y, dA4.z, dA4.w, dB4.x, dB4.y, dB4.z, dB4.w};
    const float4 tA4 = *(const float4*)(dists + base);
    const float4 tB4 = *(const float4*)(dists + base + 4);
    const int4 iA4 = *(const int4*)(sidx + base);
    const int4 iB4 = *(const int4*)(sidx + base + 4);
    // fold miss-mask into the 7*dists factor: fe = relu(sigma)*dst7, dst7=0 at misses
    float dst7[8] = {tA4.x * 7.f, tA4.y * 7.f, tA4.z * 7.f, tA4.w * 7.f,
                     tB4.x * 7.f, tB4.y * 7.f, tB4.z * 7.f, tB4.w * 7.f};
    if (iA4.x == -1) dst7[0] = 0.f;
    if (iA4.y == -1) dst7[1] = 0.f;
    if (iA4.z == -1) dst7[2] = 0.f;
    if (iA4.w == -1) dst7[3] = 0.f;
    if (iB4.x == -1) dst7[4] = 0.f;
    if (iB4.y == -1) dst7[5] = 0.f;
    if (iB4.z == -1) dst7[6] = 0.f;
    if (iB4.w == -1) dst7[7] = 0.f;

    const float* ts = s_ts[w];

    // --- view-direction rgb bias ---
    const float dt0 = rd0 * W_dir[0] + rd1 * W_dir[3] + rd2 * W_dir[6] + b_rgb[0];
    const float dt1 = rd0 * W_dir[1] + rd1 * W_dir[4] + rd2 * W_dir[7] + b_rgb[1];
    const float dt2 = rd0 * W_dir[2] + rd1 * W_dir[5] + rd2 * W_dir[8] + b_rgb[2];

    // --- rank for first sample; cache next threshold in a register ---
    int c;
    {
        const float d = dep[0];
        if (ts[63] <= d) c = 64;
        else {
            c = 0;
            if (ts[c + 31] <= d) c += 32;
            if (ts[c + 15] <= d) c += 16;
            if (ts[c + 7]  <= d) c += 8;
            if (ts[c + 3]  <= d) c += 4;
            if (ts[c + 1]  <= d) c += 2;
            if (ts[c]      <= d) c += 1;
        }
    }
    float nxt = (c < 64) ? ts[c] : 3.4e38f;
    float4 TS = s_TS[w][c];
    float4 TD = s_TD[w][c];

    // --- fused per-sample loop; q streamed to shared (unscaled) ---
    float* qrow = s_q[w] + lane * 9;
    float qs = 0.f, qd = 0.f, qc0 = 0.f, qc1 = 0.f, qc2 = 0.f;
    float run = 1.f;
#pragma unroll
    for (int s = 0; s < 8; ++s) {
        const float d = dep[s];
        if (d >= nxt) {
            do { ++c; } while (c < 64 && ts[c] <= d);
            nxt = (c < 64) ? ts[c] : 3.4e38f;
            TS = s_TS[w][c];
            TD = s_TD[w][c];
        }
        const float sigma = TS.x + d * TD.x;
        const float l0 = TS.y + d * TD.y;
        const float l1 = TS.z + d * TD.z;
        const float l2 = TS.w + d * TD.w;

        const float fe = fmaxf(sigma, 0.f) * dst7[s];
        const float es = __expf(-fe);
        const float qq = (1.f - es) * run;
        run *= es;
        qrow[s] = qq;

        qs += qq;
        qd += d * qq;
        const float r0 = fast_sigmoid(l0 + dt0);
        const float r1 = fast_sigmoid(l1 + dt1);
        const float r2 = fast_sigmoid(l2 + dt2);
        qc0 += r0 * qq;
        qc1 += r1 * qq;
        qc2 += r2 * qq;
    }

    // --- warp multiplicative exclusive scan of lane products ---
    float incl = run;
#pragma unroll
    for (int off = 1; off < 32; off <<= 1) {
        float v = __shfl_up_sync(FULL, incl, off);
        if (lane >= off) incl *= v;
    }
    float excl = __shfl_up_sync(FULL, incl, 1);
    if (lane == 0) excl = 1.f;
    s_ex[w][lane] = excl;

    float psum = excl * qs;
    float dsum = excl * qd;
    float cs0  = excl * qc0;
    float cs1  = excl * qc1;
    float cs2  = excl * qc2;

    __syncwarp();   // q staging + excl visible warp-wide

    // --- coalesced probs stores: p[m] = excl[owner] * q[m] ---
    float* orow = out + (long)ray * OUTW;
#pragma unroll
    for (int i = 0; i < 8; ++i) {
        const int m = i * 32 + lane;
        orow[5 + m] = s_ex[w][m >> 3] * s_q[w][(m >> 3) * 9 + (m & 7)];
    }

    // --- warp reductions for header values ---
#pragma unroll
    for (int off = 16; off; off >>= 1) {
        psum += __shfl_xor_sync(FULL, psum, off);
        dsum += __shfl_xor_sync(FULL, dsum, off);
        cs0  += __shfl_xor_sync(FULL, cs0, off);
        cs1  += __shfl_xor_sync(FULL, cs1, off);
        cs2  += __shfl_xor_sync(FULL, cs2, off);
    }
    if (lane == 0) {
        orow[0] = cs0;
        orow[1] = cs1;
        orow[2] = cs2;
        orow[3] = dsum;
        orow[4] = 1.f - psum;
    }
}

extern "C" void kernel_launch(void* const* d_in, const int* in_sizes, int n_in,
                              void* d_out, int out_size) {
    const float* ray_start = (const float*)d_in[0];
    const float* ray_dir   = (const float*)d_in[1];
    const float* depth     = (const float*)d_in[2];
    const float* dists     = (const float*)d_in[3];
    const int*   sidx      = (const int*)d_in[4];
    const float* W1        = (const float*)d_in[5];
    const float* b1        = (const float*)d_in[6];
    const float* w_sigma   = (const float*)d_in[7];
    const float* W_rgb     = (const float*)d_in[8];
    const float* W_dir     = (const float*)d_in[9];
    const float* b_rgb     = (const float*)d_in[10];
    float* out = (float*)d_out;

    vr_kernel<<<N_RAYS / 8, 256>>>(ray_start, ray_dir, depth, dists, sidx,
                                   W1, b1, w_sigma, W_rgb, W_dir, b_rgb, out);
}

// round 11
// speedup vs baseline: 1.2896x; 1.2896x over previous
#include <cuda_runtime.h>

#define N_RAYS   8192
#define P        256
#define HID      64
#define OUTW     261   // 3 rgb + depth + missed + 256 probs
#define FULL     0xffffffffu

__device__ __forceinline__ float4 f4add(float4 a, float4 b) {
    return make_float4(a.x + b.x, a.y + b.y, a.z + b.z, a.w + b.w);
}
__device__ __forceinline__ float4 shflup4(float4 v, int off) {
    return make_float4(__shfl_up_sync(FULL, v.x, off), __shfl_up_sync(FULL, v.y, off),
                       __shfl_up_sync(FULL, v.z, off), __shfl_up_sync(FULL, v.w, off));
}
__device__ __forceinline__ float fast_sigmoid(float x) {
    float t;
    asm("tanh.approx.f32 %0, %1;" : "=f"(t) : "f"(0.5f * x));
    return fmaf(t, 0.5f, 0.5f);
}

// Per-warp scratch: prefix tables live through the sample loop; the probs
// staging buffer is only used afterwards, so it aliases the same storage.
union WarpScratch {
    struct { float4 TS[65]; float4 TD[65]; } t;   // 2080 B
    float pb[288];                                 // 1152 B (stride-9 staging)
};

__global__ __launch_bounds__(256, 5) void vr_kernel(
    const float* __restrict__ ray_start,   // [N,3]
    const float* __restrict__ ray_dir,     // [N,3]
    const float* __restrict__ depth,       // [N,P]
    const float* __restrict__ dists,       // [N,P]
    const int*   __restrict__ sidx,        // [N,P]
    const float* __restrict__ W1,          // [3,HID]
    const float* __restrict__ b1,          // [HID]
    const float* __restrict__ w_sigma,     // [HID]
    const float* __restrict__ W_rgb,       // [HID,3]
    const float* __restrict__ W_dir,       // [3,3]
    const float* __restrict__ b_rgb,       // [3]
    float*       __restrict__ out)         // [N,OUTW]
{
    __shared__ float s_ts[8][64];
    __shared__ WarpScratch ws[8];

    const int tid  = threadIdx.x;
    const int w    = tid >> 5;
    const int lane = tid & 31;
    const int ray  = blockIdx.x * 8 + w;

    // --- per-ray scalars ---
    const float rs0 = ray_start[ray * 3 + 0];
    const float rs1 = ray_start[ray * 3 + 1];
    const float rs2 = ray_start[ray * 3 + 2];
    const float rd0 = ray_dir[ray * 3 + 0];
    const float rd1 = ray_dir[ray * 3 + 1];
    const float rd2 = ray_dir[ray * 3 + 2];

    // --- per-unit setup: lane owns units uA=lane, uB=lane+32 ---
    float kA, kB;
    float4 sgSA, sgDA, sgSB, sgDB;
    float4 negS = make_float4(0.f, 0.f, 0.f, 0.f);
    float4 negD = make_float4(0.f, 0.f, 0.f, 0.f);

#pragma unroll
    for (int half = 0; half < 2; ++half) {
        const int u = lane + half * 32;
        const float w1x = W1[u], w1y = W1[HID + u], w1z = W1[2 * HID + u];
        const float S = b1[u] + rs0 * w1x + rs1 * w1y + rs2 * w1z;
        const float D = rd0 * w1x + rd1 * w1y + rd2 * w1z;
        const float wsg = w_sigma[u];
        const float wr0 = W_rgb[u * 3 + 0];
        const float wr1 = W_rgb[u * 3 + 1];
        const float wr2 = W_rgb[u * 3 + 2];
        float t;
        int isPos;
        if (D > 0.f)      { t = __fdividef(-S, D); isPos = 1; }
        else if (D < 0.f) { t = __fdividef(-S, D); isPos = 0; }
        else              { t = (S > 0.f) ? -1e30f : 1e30f; isPos = 1; }
        const float sgn = isPos ? 1.f : -1.f;
        float4 pS = make_float4(wsg * S, wr0 * S, wr1 * S, wr2 * S);
        float4 pD = make_float4(wsg * D, wr0 * D, wr1 * D, wr2 * D);
        if (!isPos) {
            negS = f4add(negS, pS);
            negD = f4add(negD, pD);
        }
        float4 gS = make_float4(sgn * pS.x, sgn * pS.y, sgn * pS.z, sgn * pS.w);
        float4 gD = make_float4(sgn * pD.x, sgn * pD.y, sgn * pD.z, sgn * pD.w);
        if (half == 0) { kA = t; sgSA = gS; sgDA = gD; }
        else           { kB = t; sgSB = gS; sgDB = gD; }
    }

    // --- warp reduction: neg-group totals (8 channels) ---
#pragma unroll
    for (int off = 16; off; off >>= 1) {
        negS.x += __shfl_xor_sync(FULL, negS.x, off);
        negS.y += __shfl_xor_sync(FULL, negS.y, off);
        negS.z += __shfl_xor_sync(FULL, negS.z, off);
        negS.w += __shfl_xor_sync(FULL, negS.w, off);
        negD.x += __shfl_xor_sync(FULL, negD.x, off);
        negD.y += __shfl_xor_sync(FULL, negD.y, off);
        negD.z += __shfl_xor_sync(FULL, negD.z, off);
        negD.w += __shfl_xor_sync(FULL, negD.w, off);
    }

    // --- counting rank (ties by id) ---
    int rA = 0, rB = 0;
#pragma unroll
    for (int src = 0; src < 32; ++src) {
        const float oA = __shfl_sync(FULL, kA, src);
        const float oB = __shfl_sync(FULL, kB, src);
        rA += (oA < kA) | ((oA == kA) & (src < lane));
        rA += (oB < kA);
        rB += (oA < kB) | (oA == kB);
        rB += (oB < kB) | ((oB == kB) & (src < lane));
    }

    // --- scatter signed payloads into sorted slots ---
    s_ts[w][rA] = kA;
    ws[w].t.TS[rA] = sgSA;
    ws[w].t.TD[rA] = sgDA;
    s_ts[w][rB] = kB;
    ws[w].t.TS[rB] = sgSB;
    ws[w].t.TD[rB] = sgDB;
    __syncwarp();

    // --- 8-channel exclusive scan over 64 slots, bake totN into base ---
    const int p0 = 2 * lane, p1 = p0 + 1;
    const float4 aS0 = ws[w].t.TS[p0], aS1 = ws[w].t.TS[p1];
    const float4 aD0 = ws[w].t.TD[p0], aD1 = ws[w].t.TD[p1];

    float4 iS = f4add(aS0, aS1);
    float4 iD = f4add(aD0, aD1);
#pragma unroll
    for (int off = 1; off < 32; off <<= 1) {
        float4 tS = shflup4(iS, off);
        float4 tD = shflup4(iD, off);
        if (lane >= off) {
            iS = f4add(iS, tS);
            iD = f4add(iD, tD);
        }
    }
    float4 eS = shflup4(iS, 1);
    float4 eD = shflup4(iD, 1);
    if (lane == 0) {
        eS = make_float4(0.f, 0.f, 0.f, 0.f);
        eD = make_float4(0.f, 0.f, 0.f, 0.f);
    }
    __syncwarp();
    const float4 b0S = f4add(negS, eS);
    const float4 b0D = f4add(negD, eD);
    ws[w].t.TS[p0] = b0S;  ws[w].t.TS[p1] = f4add(b0S, aS0);
    ws[w].t.TD[p0] = b0D;  ws[w].t.TD[p1] = f4add(b0D, aD0);
    if (lane == 31) {
        ws[w].t.TS[64] = f4add(negS, iS);
        ws[w].t.TD[64] = f4add(negD, iD);
    }
    __syncwarp();

    // --- load this lane's 8 contiguous samples ---
    const int base = ray * P + lane * 8;
    const float4 dA4 = *(const float4*)(depth + base);
    const float4 dB4 = *(const float4*)(depth + base + 4);
    const float dep[8] = {dA4.x, dA4.y, dA4.z, dA4.w, dB4.x, dB4.y, dB4.z, dB4.w};
    const float4 tA4 = *(const float4*)(dists + base);
    const float4 tB4 = *(const float4*)(dists + base + 4);
    const int4 iA4 = *(const int4*)(sidx + base);
    const int4 iB4 = *(const int4*)(sidx + base + 4);
    // fold miss-mask into the 7*dists factor: fe = relu(sigma)*dst7, dst7=0 at misses
    float dst7[8] = {tA4.x * 7.f, tA4.y * 7.f, tA4.z * 7.f, tA4.w * 7.f,
                     tB4.x * 7.f, tB4.y * 7.f, tB4.z * 7.f, tB4.w * 7.f};
    if (iA4.x == -1) dst7[0] = 0.f;
    if (iA4.y == -1) dst7[1] = 0.f;
    if (iA4.z == -1) dst7[2] = 0.f;
    if (iA4.w == -1) dst7[3] = 0.f;
    if (iB4.x == -1) dst7[4] = 0.f;
    if (iB4.y == -1) dst7[5] = 0.f;
    if (iB4.z == -1) dst7[6] = 0.f;
    if (iB4.w == -1) dst7[7] = 0.f;

    const float* ts = s_ts[w];

    // --- view-direction rgb bias ---
    const float dt0 = rd0 * W_dir[0] + rd1 * W_dir[3] + rd2 * W_dir[6] + b_rgb[0];
    const float dt1 = rd0 * W_dir[1] + rd1 * W_dir[4] + rd2 * W_dir[7] + b_rgb[1];
    const float dt2 = rd0 * W_dir[2] + rd1 * W_dir[5] + rd2 * W_dir[8] + b_rgb[2];

    // --- rank for first sample; cache next threshold in a register ---
    int c;
    {
        const float d = dep[0];
        if (ts[63] <= d) c = 64;
        else {
            c = 0;
            if (ts[c + 31] <= d) c += 32;
            if (ts[c + 15] <= d) c += 16;
            if (ts[c + 7]  <= d) c += 8;
            if (ts[c + 3]  <= d) c += 4;
            if (ts[c + 1]  <= d) c += 2;
            if (ts[c]      <= d) c += 1;
        }
    }
    float nxt = (c < 64) ? ts[c] : 3.4e38f;
    float4 TS = ws[w].t.TS[c];
    float4 TD = ws[w].t.TD[c];

    // --- fused per-sample loop (q kept in registers, as in the R8 winner) ---
    float q[8];
    float qs = 0.f, qd = 0.f, qc0 = 0.f, qc1 = 0.f, qc2 = 0.f;
    float run = 1.f;
#pragma unroll
    for (int s = 0; s < 8; ++s) {
        const float d = dep[s];
        if (d >= nxt) {
            do { ++c; } while (c < 64 && ts[c] <= d);
            nxt = (c < 64) ? ts[c] : 3.4e38f;
            TS = ws[w].t.TS[c];
            TD = ws[w].t.TD[c];
        }
        const float sigma = TS.x + d * TD.x;
        const float l0 = TS.y + d * TD.y;
        const float l1 = TS.z + d * TD.z;
        const float l2 = TS.w + d * TD.w;

        const float fe = fmaxf(sigma, 0.f) * dst7[s];
        const float es = __expf(-fe);
        const float qq = (1.f - es) * run;
        run *= es;
        q[s] = qq;

        qs += qq;
        qd += d * qq;
        const float r0 = fast_sigmoid(l0 + dt0);
        const float r1 = fast_sigmoid(l1 + dt1);
        const float r2 = fast_sigmoid(l2 + dt2);
        qc0 += r0 * qq;
        qc1 += r1 * qq;
        qc2 += r2 * qq;
    }

    // --- warp multiplicative exclusive scan of lane products ---
    float incl = run;
#pragma unroll
    for (int off = 1; off < 32; off <<= 1) {
        float v = __shfl_up_sync(FULL, incl, off);
        if (lane >= off) incl *= v;
    }
    float excl = __shfl_up_sync(FULL, incl, 1);
    if (lane == 0) excl = 1.f;

    float psum = excl * qs;
    float dsum = excl * qd;
    float cs0  = excl * qc0;
    float cs1  = excl * qc1;
    float cs2  = excl * qc2;

    // --- probs staging in the ALIASED buffer (tables are dead now) ---
    __syncwarp();                  // all table reads complete before overwrite
    {
        float* pb = ws[w].pb;
        const int sb = lane * 9;
#pragma unroll
        for (int s = 0; s < 8; ++s) pb[sb + s] = excl * q[s];
        __syncwarp();
        float* orow = out + (long)ray * OUTW;
#pragma unroll
        for (int i = 0; i < 8; ++i) {
            const int m = i * 32 + lane;
            orow[5 + m] = pb[(m >> 3) * 9 + (m & 7)];
        }

#pragma unroll
        for (int off = 16; off; off >>= 1) {
            psum += __shfl_xor_sync(FULL, psum, off);
            dsum += __shfl_xor_sync(FULL, dsum, off);
            cs0  += __shfl_xor_sync(FULL, cs0, off);
            cs1  += __shfl_xor_sync(FULL, cs1, off);
            cs2  += __shfl_xor_sync(FULL, cs2, off);
        }
        if (lane == 0) {
            orow[0] = cs0;
            orow[1] = cs1;
            orow[2] = cs2;
            orow[3] = dsum;
            orow[4] = 1.f - psum;
        }
    }
}

extern "C" void kernel_launch(void* const* d_in, const int* in_sizes, int n_in,
                              void* d_out, int out_size) {
    const float* ray_start = (const float*)d_in[0];
    const float* ray_dir   = (const float*)d_in[1];
    const float* depth     = (const float*)d_in[2];
    const float* dists     = (const float*)d_in[3];
    const int*   sidx      = (const int*)d_in[4];
    const float* W1        = (const float*)d_in[5];
    const float* b1        = (const float*)d_in[6];
    const float* w_sigma   = (const float*)d_in[7];
    const float* W_rgb     = (const float*)d_in[8];
    const float* W_dir     = (const float*)d_in[9];
    const float* b_rgb     = (const float*)d_in[10];
    float* out = (float*)d_out;

    vr_kernel<<<N_RAYS / 8, 256>>>(ray_start, ray_dir, depth, dists, sidx,
                                   W1, b1, w_sigma, W_rgb, W_dir, b_rgb, out);
}

// round 13
// speedup vs baseline: 1.3034x; 1.0107x over previous
#include <cuda_runtime.h>

#define N_RAYS   8192
#define P        256
#define HID      64
#define OUTW     261   // 3 rgb + depth + missed + 256 probs
#define FULL     0xffffffffu
#define NW       4     // warps per block

typedef unsigned long long ull;

__device__ __forceinline__ ull pack2(float x, float y) {
    ull r;
    asm("mov.b64 %0, {%1, %2};" : "=l"(r) : "f"(x), "f"(y));
    return r;
}
__device__ __forceinline__ void unpack2(ull a, float& x, float& y) {
    asm("mov.b64 {%0, %1}, %2;" : "=f"(x), "=f"(y) : "l"(a));
}
__device__ __forceinline__ ull fma2(ull a, ull b, ull c) {
    ull d;
    asm("fma.rn.f32x2 %0, %1, %2, %3;" : "=l"(d) : "l"(a), "l"(b), "l"(c));
    return d;
}
__device__ __forceinline__ ull add2(ull a, ull b) {
    ull d;
    asm("add.rn.f32x2 %0, %1, %2;" : "=l"(d) : "l"(a), "l"(b));
    return d;
}
__device__ __forceinline__ ull shflxor64(ull v, int m) {
    unsigned lo = (unsigned)v, hi = (unsigned)(v >> 32);
    lo = __shfl_xor_sync(FULL, lo, m);
    hi = __shfl_xor_sync(FULL, hi, m);
    return ((ull)hi << 32) | lo;
}
__device__ __forceinline__ unsigned f2u(float f) {   // monotone float->uint
    int x = __float_as_int(f);
    return (unsigned)(x ^ ((x >> 31) | 0x80000000));
}
__device__ __forceinline__ float4 f4add(float4 a, float4 b) {
    return make_float4(a.x + b.x, a.y + b.y, a.z + b.z, a.w + b.w);
}
__device__ __forceinline__ float4 shflup4(float4 v, int off) {
    return make_float4(__shfl_up_sync(FULL, v.x, off), __shfl_up_sync(FULL, v.y, off),
                       __shfl_up_sync(FULL, v.z, off), __shfl_up_sync(FULL, v.w, off));
}
__device__ __forceinline__ float fast_sigmoid(float x) {
    float t;
    asm("tanh.approx.f32 %0, %1;" : "=f"(t) : "f"(0.5f * x));
    return fmaf(t, 0.5f, 0.5f);
}

// Per-warp scratch: prefix tables live through the sample loop; the probs
// staging buffer is only used afterwards, so it aliases the same storage.
union WarpScratch {
    struct { float4 TS[65]; float4 TD[65]; } t;   // 2080 B
    float pb[288];                                 // 1152 B (stride-9 staging)
};

__global__ __launch_bounds__(128, 10) void vr_kernel(
    const float* __restrict__ ray_start,   // [N,3]
    const float* __restrict__ ray_dir,     // [N,3]
    const float* __restrict__ depth,       // [N,P]
    const float* __restrict__ dists,       // [N,P]
    const int*   __restrict__ sidx,        // [N,P]
    const float* __restrict__ W1,          // [3,HID]
    const float* __restrict__ b1,          // [HID]
    const float* __restrict__ w_sigma,     // [HID]
    const float* __restrict__ W_rgb,       // [HID,3]
    const float* __restrict__ W_dir,       // [3,3]
    const float* __restrict__ b_rgb,       // [3]
    float*       __restrict__ out)         // [N,OUTW]
{
    __shared__ float s_ts[NW][65];                 // sorted keys + INF sentinel
    __shared__ WarpScratch wsc[NW];
    __shared__ unsigned char s_slot[NW][64];       // unit id -> sorted slot

    const int tid  = threadIdx.x;
    const int w    = tid >> 5;
    const int lane = tid & 31;
    const int ray  = blockIdx.x * NW + w;

    // --- per-ray scalars ---
    const float rs0 = ray_start[ray * 3 + 0];
    const float rs1 = ray_start[ray * 3 + 1];
    const float rs2 = ray_start[ray * 3 + 2];
    const float rd0 = ray_dir[ray * 3 + 0];
    const float rd1 = ray_dir[ray * 3 + 1];
    const float rd2 = ray_dir[ray * 3 + 2];

    // --- per-unit setup: lane owns units uA=lane, uB=lane+32 ---
    float kA, kB;
    ull sA0, sA1, dA0, dA1, sB0, sB1, dB0, dB1;    // signed payload (packed f32x2)
    ull nS0 = 0, nS1 = 0, nD0 = 0, nD1 = 0;        // neg-group totals (packed)

#pragma unroll
    for (int half = 0; half < 2; ++half) {
        const int u = lane + half * 32;
        const float w1x = W1[u], w1y = W1[HID + u], w1z = W1[2 * HID + u];
        const float S = b1[u] + rs0 * w1x + rs1 * w1y + rs2 * w1z;
        const float D = rd0 * w1x + rd1 * w1y + rd2 * w1z;
        const float wsg = w_sigma[u];
        const float wr0 = W_rgb[u * 3 + 0];
        const float wr1 = W_rgb[u * 3 + 1];
        const float wr2 = W_rgb[u * 3 + 2];
        float t;
        bool neg;
        if (D > 0.f)      { t = __fdividef(-S, D); neg = false; }
        else if (D < 0.f) { t = __fdividef(-S, D); neg = true; }
        else              { t = (S > 0.f) ? -1e30f : 1e30f; neg = false; }
        const float sgn = neg ? -1.f : 1.f;
        const float Ss = sgn * S, Ds = sgn * D;
        ull s0 = pack2(wsg * Ss, wr0 * Ss);
        ull s1 = pack2(wr1 * Ss, wr2 * Ss);
        ull d0 = pack2(wsg * Ds, wr0 * Ds);
        ull d1 = pack2(wr1 * Ds, wr2 * Ds);
        const float m = neg ? -1.f : 0.f;        // neg: unsigned pay = -signed
        const ull m2 = pack2(m, m);
        nS0 = fma2(s0, m2, nS0);
        nS1 = fma2(s1, m2, nS1);
        nD0 = fma2(d0, m2, nD0);
        nD1 = fma2(d1, m2, nD1);
        if (half == 0) { kA = t; sA0 = s0; sA1 = s1; dA0 = d0; dA1 = d1; }
        else           { kB = t; sB0 = s0; sB1 = s1; dB0 = d0; dB1 = d1; }
    }

    // --- warp reduction: neg-group totals (packed f32x2, unconditional adds) ---
#pragma unroll
    for (int off = 16; off; off >>= 1) {
        nS0 = add2(nS0, shflxor64(nS0, off));
        nS1 = add2(nS1, shflxor64(nS1, off));
        nD0 = add2(nD0, shflxor64(nD0, off));
        nD1 = add2(nD1, shflxor64(nD1, off));
    }
    float4 negS, negD;
    unpack2(nS0, negS.x, negS.y);
    unpack2(nS1, negS.z, negS.w);
    unpack2(nD0, negD.x, negD.y);
    unpack2(nD1, negD.z, negD.w);

    // --- bitonic sort of 64 (key,id) pairs, 2 per lane, index i = 2*lane + r ---
    ull v0 = ((ull)f2u(kA) << 32) | (unsigned)lane;
    ull v1 = ((ull)f2u(kB) << 32) | (unsigned)(lane + 32);
#pragma unroll
    for (int k = 2; k <= 64; k <<= 1) {
        const bool asc = (lane & (k >> 1)) == 0;
#pragma unroll
        for (int j = k >> 1; j > 1; j >>= 1) {      // cross-lane steps
            const int m = j >> 1;
            const bool keepMin = (((lane & m) == 0) == asc);
            ull p0 = shflxor64(v0, m);
            ull p1 = shflxor64(v1, m);
            v0 = keepMin ? (v0 < p0 ? v0 : p0) : (v0 < p0 ? p0 : v0);
            v1 = keepMin ? (v1 < p1 ? v1 : p1) : (v1 < p1 ? p1 : v1);
        }
        {                                           // j == 1: in-register CE
            ull lo = v0 < v1 ? v0 : v1;
            ull hi = v0 < v1 ? v1 : v0;
            v0 = asc ? lo : hi;
            v1 = asc ? hi : lo;
        }
    }

    // --- invert permutation: unit id -> sorted slot ---
    s_slot[w][(unsigned)v0 & 63] = (unsigned char)(2 * lane);
    s_slot[w][(unsigned)v1 & 63] = (unsigned char)(2 * lane + 1);
    __syncwarp();
    const int rA = s_slot[w][lane];
    const int rB = s_slot[w][lane + 32];

    // --- scatter keys + signed payloads into sorted slots ---
    s_ts[w][rA] = kA;
    s_ts[w][rB] = kB;
    {
        ull* pA  = reinterpret_cast<ull*>(&wsc[w].t.TS[rA]);
        pA[0] = sA0;  pA[1] = sA1;
        ull* pAD = reinterpret_cast<ull*>(&wsc[w].t.TD[rA]);
        pAD[0] = dA0; pAD[1] = dA1;
        ull* pB  = reinterpret_cast<ull*>(&wsc[w].t.TS[rB]);
        pB[0] = sB0;  pB[1] = sB1;
        ull* pBD = reinterpret_cast<ull*>(&wsc[w].t.TD[rB]);
        pBD[0] = dB0; pBD[1] = dB1;
    }
    if (lane == 0) s_ts[w][64] = __int_as_float(0x7f800000);   // +INF sentinel
    __syncwarp();

    // --- 8-channel exclusive scan over 64 slots, bake negTot into base ---
    const int p0 = 2 * lane, p1 = p0 + 1;
    const float4 aS0 = wsc[w].t.TS[p0], aS1 = wsc[w].t.TS[p1];
    const float4 aD0 = wsc[w].t.TD[p0], aD1 = wsc[w].t.TD[p1];

    float4 iS = f4add(aS0, aS1);
    float4 iD = f4add(aD0, aD1);
#pragma unroll
    for (int off = 1; off < 32; off <<= 1) {
        float4 tS = shflup4(iS, off);
        float4 tD = shflup4(iD, off);
        if (lane >= off) {
            iS = f4add(iS, tS);
            iD = f4add(iD, tD);
        }
    }
    float4 eS = shflup4(iS, 1);
    float4 eD = shflup4(iD, 1);
    if (lane == 0) {
        eS = make_float4(0.f, 0.f, 0.f, 0.f);
        eD = make_float4(0.f, 0.f, 0.f, 0.f);
    }
    __syncwarp();
    const float4 b0S = f4add(negS, eS);
    const float4 b0D = f4add(negD, eD);
    wsc[w].t.TS[p0] = b0S;  wsc[w].t.TS[p1] = f4add(b0S, aS0);
    wsc[w].t.TD[p0] = b0D;  wsc[w].t.TD[p1] = f4add(b0D, aD0);
    if (lane == 31) {
        wsc[w].t.TS[64] = f4add(negS, iS);
        wsc[w].t.TD[64] = f4add(negD, iD);
    }
    __syncwarp();

    // --- load this lane's 8 contiguous samples ---
    const int base = ray * P + lane * 8;
    const float4 dA4 = *(const float4*)(depth + base);
    const float4 dB4 = *(const float4*)(depth + base + 4);
    const float dep[8] = {dA4.x, dA4.y, dA4.z, dA4.w, dB4.x, dB4.y, dB4.z, dB4.w};
    const float4 tA4 = *(const float4*)(dists + base);
    const float4 tB4 = *(const float4*)(dists + base + 4);
    const int4 iA4 = *(const int4*)(sidx + base);
    const int4 iB4 = *(const int4*)(sidx + base + 4);
    // fold miss-mask into the 7*dists factor
    float dst7[8] = {tA4.x * 7.f, tA4.y * 7.f, tA4.z * 7.f, tA4.w * 7.f,
                     tB4.x * 7.f, tB4.y * 7.f, tB4.z * 7.f, tB4.w * 7.f};
    if (iA4.x == -1) dst7[0] = 0.f;
    if (iA4.y == -1) dst7[1] = 0.f;
    if (iA4.z == -1) dst7[2] = 0.f;
    if (iA4.w == -1) dst7[3] = 0.f;
    if (iB4.x == -1) dst7[4] = 0.f;
    if (iB4.y == -1) dst7[5] = 0.f;
    if (iB4.z == -1) dst7[6] = 0.f;
    if (iB4.w == -1) dst7[7] = 0.f;

    const float* ts = s_ts[w];

    // --- view-direction rgb bias ---
    const float dt0 = rd0 * W_dir[0] + rd1 * W_dir[3] + rd2 * W_dir[6] + b_rgb[0];
    const float dt1 = rd0 * W_dir[1] + rd1 * W_dir[4] + rd2 * W_dir[7] + b_rgb[1];
    const float dt2 = rd0 * W_dir[2] + rd1 * W_dir[5] + rd2 * W_dir[8] + b_rgb[2];

    // --- rank for first sample (binary search), then sentinel-guarded advance ---
    int c;
    {
        const float d = dep[0];
        if (ts[63] <= d) c = 64;
        else {
            c = 0;
            if (ts[c + 31] <= d) c += 32;
            if (ts[c + 15] <= d) c += 16;
            if (ts[c + 7]  <= d) c += 8;
            if (ts[c + 3]  <= d) c += 4;
            if (ts[c + 1]  <= d) c += 2;
            if (ts[c]      <= d) c += 1;
        }
    }
    float nxt = ts[c];                     // ts[64] = +INF sentinel
    float4 TS = wsc[w].t.TS[c];
    float4 TD = wsc[w].t.TD[c];

    // --- fused per-sample loop ---
    float q[8];
    float qs = 0.f, qd = 0.f, qc0 = 0.f, qc1 = 0.f, qc2 = 0.f;
    float run = 1.f;
#pragma unroll
    for (int s = 0; s < 8; ++s) {
        const float d = dep[s];
        if (nxt <= d) {
            do { ++c; nxt = ts[c]; } while (nxt <= d);
            TS = wsc[w].t.TS[c];
            TD = wsc[w].t.TD[c];
        }
        const float sigma = TS.x + d * TD.x;
        const float l0 = TS.y + d * TD.y;
        const float l1 = TS.z + d * TD.z;
        const float l2 = TS.w + d * TD.w;

        const float fe = fmaxf(sigma, 0.f) * dst7[s];
        const float es = __expf(-fe);
        const float qq = (1.f - es) * run;
        run *= es;
        q[s] = qq;

        qs += qq;
        qd += d * qq;
        const float r0 = fast_sigmoid(l0 + dt0);
        const float r1 = fast_sigmoid(l1 + dt1);
        const float r2 = fast_sigmoid(l2 + dt2);
        qc0 += r0 * qq;
        qc1 += r1 * qq;
        qc2 += r2 * qq;
    }

    // --- warp multiplicative exclusive scan of lane products ---
    float incl = run;
#pragma unroll
    for (int off = 1; off < 32; off <<= 1) {
        float v = __shfl_up_sync(FULL, incl, off);
        if (lane >= off) incl *= v;
    }
    float excl = __shfl_up_sync(FULL, incl, 1);
    if (lane == 0) excl = 1.f;

    float psum = excl * qs;
    float dsum = excl * qd;
    float cs0  = excl * qc0;
    float cs1  = excl * qc1;
    float cs2  = excl * qc2;

    // --- probs staging in the ALIASED buffer (tables are dead now) ---
    __syncwarp();                  // all table reads complete before overwrite
    {
        float* pb = wsc[w].pb;
        const int sb = lane * 9;
#pragma unroll
        for (int s = 0; s < 8; ++s) pb[sb + s] = excl * q[s];
        __syncwarp();
        float* orow = out + (long)ray * OUTW;
#pragma unroll
        for (int i = 0; i < 8; ++i) {
            const int m = i * 32 + lane;
            orow[5 + m] = pb[(m >> 3) * 9 + (m & 7)];
        }

#pragma unroll
        for (int off = 16; off; off >>= 1) {
            psum += __shfl_xor_sync(FULL, psum, off);
            dsum += __shfl_xor_sync(FULL, dsum, off);
            cs0  += __shfl_xor_sync(FULL, cs0, off);
            cs1  += __shfl_xor_sync(FULL, cs1, off);
            cs2  += __shfl_xor_sync(FULL, cs2, off);
        }
        if (lane == 0) {
            orow[0] = cs0;
            orow[1] = cs1;
            orow[2] = cs2;
            orow[3] = dsum;
            orow[4] = 1.f - psum;
        }
    }
}

extern "C" void kernel_launch(void* const* d_in, const int* in_sizes, int n_in,
                              void* d_out, int out_size) {
    const float* ray_start = (const float*)d_in[0];
    const float* ray_dir   = (const float*)d_in[1];
    const float* depth     = (const float*)d_in[2];
    const float* dists     = (const float*)d_in[3];
    const int*   sidx      = (const int*)d_in[4];
    const float* W1        = (const float*)d_in[5];
    const float* b1        = (const float*)d_in[6];
    const float* w_sigma   = (const float*)d_in[7];
    const float* W_rgb     = (const float*)d_in[8];
    const float* W_dir     = (const float*)d_in[9];
    const float* b_rgb     = (const float*)d_in[10];
    float* out = (float*)d_out;

    vr_kernel<<<N_RAYS / NW, 128>>>(ray_start, ray_dir, depth, dists, sidx,
                                    W1, b1, w_sigma, W_rgb, W_dir, b_rgb, out);
}

// round 15
// speedup vs baseline: 1.4250x; 1.0933x over previous
#include <cuda_runtime.h>

#define N_RAYS   8192
#define P        256
#define HID      64
#define OUTW     261   // 3 rgb + depth + missed + 256 probs
#define FULL     0xffffffffu
#define NW       4     // warps per block

typedef unsigned long long ull;

__device__ __forceinline__ ull pack2(float x, float y) {
    ull r;
    asm("mov.b64 %0, {%1, %2};" : "=l"(r) : "f"(x), "f"(y));
    return r;
}
__device__ __forceinline__ void unpack2(ull a, float& x, float& y) {
    asm("mov.b64 {%0, %1}, %2;" : "=f"(x), "=f"(y) : "l"(a));
}
__device__ __forceinline__ ull fma2(ull a, ull b, ull c) {
    ull d;
    asm("fma.rn.f32x2 %0, %1, %2, %3;" : "=l"(d) : "l"(a), "l"(b), "l"(c));
    return d;
}
__device__ __forceinline__ ull add2(ull a, ull b) {
    ull d;
    asm("add.rn.f32x2 %0, %1, %2;" : "=l"(d) : "l"(a), "l"(b));
    return d;
}
__device__ __forceinline__ ull shflxor64(ull v, int m) {
    unsigned lo = (unsigned)v, hi = (unsigned)(v >> 32);
    lo = __shfl_xor_sync(FULL, lo, m);
    hi = __shfl_xor_sync(FULL, hi, m);
    return ((ull)hi << 32) | lo;
}
__device__ __forceinline__ unsigned f2u(float f) {   // monotone float->uint
    int x = __float_as_int(f);
    return (unsigned)(x ^ ((x >> 31) | 0x80000000));
}
__device__ __forceinline__ float u2f(unsigned u) {   // inverse of f2u
    int x = (u & 0x80000000u) ? (int)(u ^ 0x80000000u) : (int)~u;
    return __int_as_float(x);
}
__device__ __forceinline__ float4 f4add(float4 a, float4 b) {
    return make_float4(a.x + b.x, a.y + b.y, a.z + b.z, a.w + b.w);
}
__device__ __forceinline__ float4 shflup4(float4 v, int off) {
    return make_float4(__shfl_up_sync(FULL, v.x, off), __shfl_up_sync(FULL, v.y, off),
                       __shfl_up_sync(FULL, v.z, off), __shfl_up_sync(FULL, v.w, off));
}
__device__ __forceinline__ float fast_sigmoid(float x) {
    float t;
    asm("tanh.approx.f32 %0, %1;" : "=f"(t) : "f"(0.5f * x));
    return fmaf(t, 0.5f, 0.5f);
}

// Per-warp scratch: payload-by-id, then prefix tables (same storage), then
// probs staging aliases it after the tables are dead.
union WarpScratch {
    struct { float4 TS[65]; float4 TD[65]; } t;   // 2080 B
    float pb[288];                                 // 1152 B (stride-9 staging)
};

__global__ __launch_bounds__(128, 10) void vr_kernel(
    const float* __restrict__ ray_start,   // [N,3]
    const float* __restrict__ ray_dir,     // [N,3]
    const float* __restrict__ depth,       // [N,P]
    const float* __restrict__ dists,       // [N,P]
    const int*   __restrict__ sidx,        // [N,P]
    const float* __restrict__ W1,          // [3,HID]
    const float* __restrict__ b1,          // [HID]
    const float* __restrict__ w_sigma,     // [HID]
    const float* __restrict__ W_rgb,       // [HID,3]
    const float* __restrict__ W_dir,       // [3,3]
    const float* __restrict__ b_rgb,       // [3]
    float*       __restrict__ out)         // [N,OUTW]
{
    __shared__ float s_ts[NW][66];                 // sorted keys + INF sentinel (66: float2 align)
    __shared__ WarpScratch wsc[NW];

    const int tid  = threadIdx.x;
    const int w    = tid >> 5;
    const int lane = tid & 31;
    const int ray  = blockIdx.x * NW + w;

    // --- per-ray scalars ---
    const float rs0 = ray_start[ray * 3 + 0];
    const float rs1 = ray_start[ray * 3 + 1];
    const float rs2 = ray_start[ray * 3 + 2];
    const float rd0 = ray_dir[ray * 3 + 0];
    const float rd1 = ray_dir[ray * 3 + 1];
    const float rd2 = ray_dir[ray * 3 + 2];

    // --- per-unit setup: lane owns units uA=lane, uB=lane+32 ---
    // Signed payloads stored BY UNIT ID (coalesced); gathered by sorted id later.
    float kA, kB;
    ull nS0 = 0, nS1 = 0, nD0 = 0, nD1 = 0;        // neg-group totals (packed f32x2)

#pragma unroll
    for (int half = 0; half < 2; ++half) {
        const int u = lane + half * 32;
        const float w1x = W1[u], w1y = W1[HID + u], w1z = W1[2 * HID + u];
        const float S = b1[u] + rs0 * w1x + rs1 * w1y + rs2 * w1z;
        const float D = rd0 * w1x + rd1 * w1y + rd2 * w1z;
        const float wsg = w_sigma[u];
        const float wr0 = W_rgb[u * 3 + 0];
        const float wr1 = W_rgb[u * 3 + 1];
        const float wr2 = W_rgb[u * 3 + 2];
        float t;
        bool neg;
        if (D > 0.f)      { t = __fdividef(-S, D); neg = false; }
        else if (D < 0.f) { t = __fdividef(-S, D); neg = true; }
        else              { t = (S > 0.f) ? -1e30f : 1e30f; neg = false; }
        const float sgn = neg ? -1.f : 1.f;
        const float Ss = sgn * S, Ds = sgn * D;
        float4 pS = make_float4(wsg * Ss, wr0 * Ss, wr1 * Ss, wr2 * Ss);
        float4 pD = make_float4(wsg * Ds, wr0 * Ds, wr1 * Ds, wr2 * Ds);
        wsc[w].t.TS[u] = pS;                       // by-id store (coalesced)
        wsc[w].t.TD[u] = pD;
        const float m = neg ? -1.f : 0.f;          // neg: unsigned pay = -signed
        const ull m2 = pack2(m, m);
        nS0 = fma2(pack2(pS.x, pS.y), m2, nS0);
        nS1 = fma2(pack2(pS.z, pS.w), m2, nS1);
        nD0 = fma2(pack2(pD.x, pD.y), m2, nD0);
        nD1 = fma2(pack2(pD.z, pD.w), m2, nD1);
        if (half == 0) kA = t; else kB = t;
    }

    // --- warp reduction: neg-group totals (packed f32x2) ---
#pragma unroll
    for (int off = 16; off; off >>= 1) {
        nS0 = add2(nS0, shflxor64(nS0, off));
        nS1 = add2(nS1, shflxor64(nS1, off));
        nD0 = add2(nD0, shflxor64(nD0, off));
        nD1 = add2(nD1, shflxor64(nD1, off));
    }
    float4 negS, negD;
    unpack2(nS0, negS.x, negS.y);
    unpack2(nS1, negS.z, negS.w);
    unpack2(nD0, negD.x, negD.y);
    unpack2(nD1, negD.z, negD.w);

    // --- bitonic sort of 64 packed 32-bit (key|id), 2/lane, index i=2*lane+r ---
    unsigned v0 = (f2u(kA) & 0xFFFFFFC0u) | (unsigned)lane;
    unsigned v1 = (f2u(kB) & 0xFFFFFFC0u) | (unsigned)(lane + 32);
#pragma unroll
    for (int k = 2; k <= 64; k <<= 1) {
        const bool asc = (lane & (k >> 1)) == 0;
#pragma unroll
        for (int j = k >> 1; j > 1; j >>= 1) {      // cross-lane steps
            const int m = j >> 1;
            const bool keepMin = (((lane & m) == 0) == asc);
            const unsigned p0 = __shfl_xor_sync(FULL, v0, m);
            const unsigned p1 = __shfl_xor_sync(FULL, v1, m);
            v0 = keepMin ? min(v0, p0) : max(v0, p0);
            v1 = keepMin ? min(v1, p1) : max(v1, p1);
        }
        {                                           // j == 1: in-register CE
            const unsigned lo = min(v0, v1), hi = max(v0, v1);
            v0 = asc ? lo : hi;
            v1 = asc ? hi : lo;
        }
    }

    __syncwarp();   // by-id payload stores visible before gather

    // --- gather payloads for this lane's two sorted slots (p0=2*lane, p1) ---
    const int id0 = v0 & 63, id1 = v1 & 63;
    const float4 aS0 = wsc[w].t.TS[id0], aD0 = wsc[w].t.TD[id0];
    const float4 aS1 = wsc[w].t.TS[id1], aD1 = wsc[w].t.TD[id1];

    // sorted keys (masked-float: exactly monotone), coalesced float2 store
    *(float2*)&s_ts[w][2 * lane] =
        make_float2(u2f(v0 & 0xFFFFFFC0u), u2f(v1 & 0xFFFFFFC0u));
    if (lane == 0) s_ts[w][64] = __int_as_float(0x7f800000);   // +INF sentinel

    // --- 8-channel exclusive scan over 64 slots, bake negTot into base ---
    const int p0 = 2 * lane, p1 = p0 + 1;
    float4 iS = f4add(aS0, aS1);
    float4 iD = f4add(aD0, aD1);
#pragma unroll
    for (int off = 1; off < 32; off <<= 1) {
        float4 tS = shflup4(iS, off);
        float4 tD = shflup4(iD, off);
        if (lane >= off) {
            iS = f4add(iS, tS);
            iD = f4add(iD, tD);
        }
    }
    float4 eS = shflup4(iS, 1);
    float4 eD = shflup4(iD, 1);
    if (lane == 0) {
        eS = make_float4(0.f, 0.f, 0.f, 0.f);
        eD = make_float4(0.f, 0.f, 0.f, 0.f);
    }
    __syncwarp();   // all gathers complete before tables are overwritten
    const float4 b0S = f4add(negS, eS);
    const float4 b0D = f4add(negD, eD);
    wsc[w].t.TS[p0] = b0S;  wsc[w].t.TS[p1] = f4add(b0S, aS0);
    wsc[w].t.TD[p0] = b0D;  wsc[w].t.TD[p1] = f4add(b0D, aD0);
    if (lane == 31) {
        wsc[w].t.TS[64] = f4add(negS, iS);
        wsc[w].t.TD[64] = f4add(negD, iD);
    }
    __syncwarp();

    // --- load this lane's 8 contiguous samples ---
    const int base = ray * P + lane * 8;
    const float4 dA4 = *(const float4*)(depth + base);
    const float4 dB4 = *(const float4*)(depth + base + 4);
    const float dep[8] = {dA4.x, dA4.y, dA4.z, dA4.w, dB4.x, dB4.y, dB4.z, dB4.w};
    const float4 tA4 = *(const float4*)(dists + base);
    const float4 tB4 = *(const float4*)(dists + base + 4);
    const int4 iA4 = *(const int4*)(sidx + base);
    const int4 iB4 = *(const int4*)(sidx + base + 4);
    float dst7[8] = {tA4.x * 7.f, tA4.y * 7.f, tA4.z * 7.f, tA4.w * 7.f,
                     tB4.x * 7.f, tB4.y * 7.f, tB4.z * 7.f, tB4.w * 7.f};
    if (iA4.x == -1) dst7[0] = 0.f;
    if (iA4.y == -1) dst7[1] = 0.f;
    if (iA4.z == -1) dst7[2] = 0.f;
    if (iA4.w == -1) dst7[3] = 0.f;
    if (iB4.x == -1) dst7[4] = 0.f;
    if (iB4.y == -1) dst7[5] = 0.f;
    if (iB4.z == -1) dst7[6] = 0.f;
    if (iB4.w == -1) dst7[7] = 0.f;

    const float* ts = s_ts[w];

    // --- view-direction rgb bias ---
    const float dt0 = rd0 * W_dir[0] + rd1 * W_dir[3] + rd2 * W_dir[6] + b_rgb[0];
    const float dt1 = rd0 * W_dir[1] + rd1 * W_dir[4] + rd2 * W_dir[7] + b_rgb[1];
    const float dt2 = rd0 * W_dir[2] + rd1 * W_dir[5] + rd2 * W_dir[8] + b_rgb[2];

    // --- rank for first sample (binary search), then sentinel-guarded advance ---
    int c;
    {
        const float d = dep[0];
        if (ts[63] <= d) c = 64;
        else {
            c = 0;
            if (ts[c + 31] <= d) c += 32;
            if (ts[c + 15] <= d) c += 16;
            if (ts[c + 7]  <= d) c += 8;
            if (ts[c + 3]  <= d) c += 4;
            if (ts[c + 1]  <= d) c += 2;
            if (ts[c]      <= d) c += 1;
        }
    }
    float nxt = ts[c];                     // ts[64] = +INF sentinel
    ulonglong2 TSv = *(const ulonglong2*)&wsc[w].t.TS[c];
    ulonglong2 TDv = *(const ulonglong2*)&wsc[w].t.TD[c];

    // --- fused per-sample loop (f32x2 eval) ---
    float q[8];
    float qs = 0.f, qd = 0.f, qc0 = 0.f, qc1 = 0.f, qc2 = 0.f;
    float run = 1.f;
#pragma unroll
    for (int s = 0; s < 8; ++s) {
        const float d = dep[s];
        if (nxt <= d) {
            do { ++c; nxt = ts[c]; } while (nxt <= d);
            TSv = *(const ulonglong2*)&wsc[w].t.TS[c];
            TDv = *(const ulonglong2*)&wsc[w].t.TD[c];
        }
        const ull d2 = pack2(d, d);
        float sigma, l0, l1, l2;
        unpack2(fma2(d2, TDv.x, TSv.x), sigma, l0);
        unpack2(fma2(d2, TDv.y, TSv.y), l1, l2);

        const float fe = fmaxf(sigma, 0.f) * dst7[s];
        const float es = __expf(-fe);
        const float qq = (1.f - es) * run;
        run *= es;
        q[s] = qq;

        qs += qq;
        qd += d * qq;
        const float r0 = fast_sigmoid(l0 + dt0);
        const float r1 = fast_sigmoid(l1 + dt1);
        const float r2 = fast_sigmoid(l2 + dt2);
        qc0 += r0 * qq;
        qc1 += r1 * qq;
        qc2 += r2 * qq;
    }

    // --- warp multiplicative exclusive scan of lane products ---
    float incl = run;
#pragma unroll
    for (int off = 1; off < 32; off <<= 1) {
        float v = __shfl_up_sync(FULL, incl, off);
        if (lane >= off) incl *= v;
    }
    float excl = __shfl_up_sync(FULL, incl, 1);
    if (lane == 0) excl = 1.f;

    float psum = excl * qs;
    float dsum = excl * qd;
    float cs0  = excl * qc0;
    float cs1  = excl * qc1;
    float cs2  = excl * qc2;

    // --- probs staging in the ALIASED buffer (tables are dead now) ---
    __syncwarp();                  // all table reads complete before overwrite
    {
        float* pb = wsc[w].pb;
        const int sb = lane * 9;
#pragma unroll
        for (int s = 0; s < 8; ++s) pb[sb + s] = excl * q[s];
        __syncwarp();
        float* orow = out + (long)ray * OUTW;
#pragma unroll
        for (int i = 0; i < 8; ++i) {
            const int m = i * 32 + lane;
            orow[5 + m] = pb[(m >> 3) * 9 + (m & 7)];
        }

#pragma unroll
        for (int off = 16; off; off >>= 1) {
            psum += __shfl_xor_sync(FULL, psum, off);
            dsum += __shfl_xor_sync(FULL, dsum, off);
            cs0  += __shfl_xor_sync(FULL, cs0, off);
            cs1  += __shfl_xor_sync(FULL, cs1, off);
            cs2  += __shfl_xor_sync(FULL, cs2, off);
        }
        if (lane == 0) {
            orow[0] = cs0;
            orow[1] = cs1;
            orow[2] = cs2;
            orow[3] = dsum;
            orow[4] = 1.f - psum;
        }
    }
}

extern "C" void kernel_launch(void* const* d_in, const int* in_sizes, int n_in,
                              void* d_out, int out_size) {
    const float* ray_start = (const float*)d_in[0];
    const float* ray_dir   = (const float*)d_in[1];
    const float* depth     = (const float*)d_in[2];
    const float* dists     = (const float*)d_in[3];
    const int*   sidx      = (const int*)d_in[4];
    const float* W1        = (const float*)d_in[5];
    const float* b1        = (const float*)d_in[6];
    const float* w_sigma   = (const float*)d_in[7];
    const float* W_rgb     = (const float*)d_in[8];
    const float* W_dir     = (const float*)d_in[9];
    const float* b_rgb     = (const float*)d_in[10];
    float* out = (float*)d_out;

    vr_kernel<<<N_RAYS / NW, 128>>>(ray_start, ray_dir, depth, dists, sidx,
                                    W1, b1, w_sigma, W_rgb, W_dir, b_rgb, out);
}